// round 12
// baseline (speedup 1.0000x reference)
#include <cuda_runtime.h>
#include <cstdint>

#define IN_CH   64
#define OUT_CH  64
#define GROUPS  8
#define FPG     8
#define H       256
#define WID     256
#define BATCH   8
#define TY      32
#define SM_W    260                 // padded row width, multiple of 4
#define NCHUNK  8                   // 8 chunks of 4 output rows

__device__ __forceinline__ uint32_t s2u(const void* p) {
    uint32_t a;
    asm("{ .reg .u64 t; cvta.to.shared.u64 t, %1; cvt.u32.u64 %0, t; }" : "=r"(a) : "l"(p));
    return a;
}

__global__ __launch_bounds__(256) void fused_conv_kernel(const float* __restrict__ x,
                                                         const float* __restrict__ rep,
                                                         const float* __restrict__ W,
                                                         float* __restrict__ out) {
    __shared__ float sm[(TY + 2) * SM_W];            // 35360 B, written once
    __shared__ float wsm[FPG * 9];                   // 72 dynamic weights
    __shared__ __align__(8) unsigned long long mbar[NCHUNK];

    const int tileY = blockIdx.x;       // 0..7
    const int g     = blockIdx.y;       // 0..7
    const int b     = blockIdx.z;       // 0..7
    const int tid   = threadIdx.x;
    const int y0    = tileY * TY;

    const float* xg = x + ((size_t)(b * IN_CH + g * FPG)) * (H * WID);

    if (tid == 0) {
        #pragma unroll
        for (int k = 0; k < NCHUNK; ++k) {
            uint32_t a = s2u(&mbar[k]);
            asm volatile("mbarrier.init.shared.b64 [%0], %1;" :: "r"(a), "r"(128) : "memory");
        }
    }
    __syncthreads();

    if (tid < 128) {
        // ================= PRODUCER: warps 0-3 =================
        // chunk 0: padded rows 0..5 ; chunk k>=1: padded rows 4k+2..4k+5
        for (int k = 0; k < NCHUNK; ++k) {
            const int base  = (k == 0) ? 0 : (4 * k + 2);
            const int rows  = (k == 0) ? 6 : 4;
            const int items = rows * 64;
            for (int it = tid; it < items; it += 128) {
                int r  = base + (it >> 6);
                int j4 = it & 63;
                int y = y0 + r - 1;
                y = (y < 0) ? 1 : (y > H - 1 ? H - 2 : y);   // reflect pad=1
                const float4* p = (const float4*)(xg + (size_t)y * WID + 4 * j4);
                float sx = 0.f, sy = 0.f, sz = 0.f, sw = 0.f;
                #pragma unroll
                for (int c = 0; c < FPG; ++c) {
                    float4 v = p[c * (H * WID / 4)];
                    sx += v.x; sy += v.y; sz += v.z; sw += v.w;
                }
                float* d = sm + r * SM_W + 4 * j4 + 1;       // padded col = x+1
                d[0] = sx; d[1] = sy; d[2] = sz; d[3] = sw;
            }
            // halo columns for this chunk's rows
            if (tid < 2 * rows) {
                int r = base + (tid >> 1), side = tid & 1;
                int y = y0 + r - 1;
                y = (y < 0) ? 1 : (y > H - 1 ? H - 2 : y);
                int xs = side ? (WID - 2) : 1;
                float v = 0.f;
                #pragma unroll
                for (int c = 0; c < FPG; ++c)
                    v += xg[(size_t)c * (H * WID) + (size_t)y * WID + xs];
                sm[r * SM_W + (side ? 257 : 0)] = v;
            }
            uint32_t a = s2u(&mbar[k]);
            asm volatile("mbarrier.arrive.shared.b64 _, [%0];" :: "r"(a) : "memory");
        }
    } else {
        // ================= CONSUMER: warps 4-7 =================
        const int ct = tid - 128;

        // dynamic weights: leaky_relu(rep[b] . W[g*72 + ct])
        if (ct < FPG * 9) {
            const float4* wr = (const float4*)(W + (size_t)(g * FPG * 9 + ct) * 32);
            const float4* rv = (const float4*)(rep + b * 32);
            float acc = 0.f;
            #pragma unroll
            for (int i = 0; i < 8; ++i) {
                float4 a = wr[i], r = rv[i];
                acc += a.x * r.x + a.y * r.y + a.z * r.z + a.w * r.w;
            }
            wsm[ct] = acc > 0.f ? acc : 0.1f * acc;
        }
        asm volatile("bar.sync 1, 128;" ::: "memory");       // consumer-group sync

        const int q  = ct & 63;       // x-quad
        const int r0 = ct >> 6;       // 0..1
        float* ob = out + ((size_t)(b * OUT_CH + g * FPG)) * (H * WID) + 4 * q;

        for (int k = 0; k < NCHUNK; ++k) {
            // wait for chunk k (acquire)
            {
                uint32_t a = s2u(&mbar[k]);
                uint32_t done = 0;
                do {
                    asm volatile(
                        "{ .reg .pred p;\n\t"
                        "mbarrier.try_wait.parity.acquire.cta.shared::cta.b64 p, [%1], %2, 0x989680;\n\t"
                        "selp.b32 %0, 1, 0, p; }"
                        : "=r"(done) : "r"(a), "r"(0) : "memory");
                } while (!done);
            }
            #pragma unroll
            for (int s = 0; s < 2; ++s) {
                const int rr = 4 * k + r0 + 2 * s;           // output row within tile
                float win[3][6];
                #pragma unroll
                for (int dy = 0; dy < 3; ++dy) {
                    const float4* sp = (const float4*)(sm + (rr + dy) * SM_W + 4 * q);
                    float4 a = sp[0], bb = sp[1];
                    win[dy][0] = a.x;  win[dy][1] = a.y;  win[dy][2] = a.z;  win[dy][3] = a.w;
                    win[dy][4] = bb.x; win[dy][5] = bb.y;
                }
                const int y = y0 + rr;
                #pragma unroll
                for (int o = 0; o < 8; ++o) {
                    float wo[9];
                    #pragma unroll
                    for (int j = 0; j < 9; ++j) wo[j] = wsm[o * 9 + j];
                    float ax = 0.f, ay = 0.f, az = 0.f, aw = 0.f;
                    #pragma unroll
                    for (int dy = 0; dy < 3; ++dy) {
                        #pragma unroll
                        for (int dx = 0; dx < 3; ++dx) {
                            const float wv = wo[dy * 3 + dx];
                            ax += wv * win[dy][dx + 0];
                            ay += wv * win[dy][dx + 1];
                            az += wv * win[dy][dx + 2];
                            aw += wv * win[dy][dx + 3];
                        }
                    }
                    *(float4*)(ob + (size_t)o * (H * WID) + (size_t)y * WID) =
                        make_float4(ax, ay, az, aw);
                }
            }
        }
    }
}

extern "C" void kernel_launch(void* const* d_in, const int* in_sizes, int n_in,
                              void* d_out, int out_size) {
    const float* x   = (const float*)d_in[0];
    const float* rep = (const float*)d_in[1];
    const float* W   = (const float*)d_in[2];
    float* out = (float*)d_out;

    dim3 grid(H / TY, GROUPS, BATCH);
    fused_conv_kernel<<<grid, 256>>>(x, rep, W, out);
}

// round 16
// speedup vs baseline: 1.0435x; 1.0435x over previous
#include <cuda_runtime.h>
#include <cstdint>

#define IN_CH   64
#define OUT_CH  64
#define GROUPS  8
#define FPG     8
#define H       256
#define WID     256
#define BATCH   8
#define TY      32
#define SM_W    260                    // A tile padded row width (floats)
#define B_W     256                    // B (shifted) tile row width (floats)

#define A_FLOATS ((TY + 2) * SM_W)     // 8840
#define B_FLOATS ((TY + 2) * B_W)      // 8704
#define SMEM_BYTES (A_FLOATS * 4 + B_FLOATS * 4 + FPG * 9 * 8)   // 70752

__device__ __forceinline__ void fma2(uint64_t& d, uint64_t a, uint64_t b) {
    asm("fma.rn.f32x2 %0, %1, %2, %3;" : "=l"(d) : "l"(a), "l"(b), "l"(d));
}
__device__ __forceinline__ void unpk(float& lo, float& hi, uint64_t v) {
    asm("mov.b64 {%0, %1}, %2;" : "=f"(lo), "=f"(hi) : "l"(v));
}

__global__ __launch_bounds__(256) void fused_conv_kernel(const float* __restrict__ x,
                                                         const float* __restrict__ rep,
                                                         const float* __restrict__ W,
                                                         float* __restrict__ out) {
    extern __shared__ __align__(16) float smem[];
    float*    smA  = smem;                           // [34][260], smA[r][p] = s_padded[p]
    float*    smB  = smem + A_FLOATS;                // [34][256], smB[r][i] = s_padded[i+1]
    uint64_t* wsm2 = (uint64_t*)(smem + A_FLOATS + B_FLOATS);   // 72 packed (w,w)

    const int tileY = blockIdx.x;       // 0..7
    const int g     = blockIdx.y;       // 0..7
    const int b     = blockIdx.z;       // 0..7
    const int tid   = threadIdx.x;

    const float* xg = x + ((size_t)(b * IN_CH + g * FPG)) * (H * WID);

    // ---- weights: leaky_relu(rep[b] . W[row]), packed (w,w) ----
    if (tid < FPG * 9) {
        const float4* wr = (const float4*)(W + (size_t)(g * FPG * 9 + tid) * 32);
        const float4* rv = (const float4*)(rep + b * 32);
        float acc = 0.f;
        #pragma unroll
        for (int i = 0; i < 8; ++i) {
            float4 a = wr[i], r = rv[i];
            acc += a.x * r.x + a.y * r.y + a.z * r.z + a.w * r.w;
        }
        float lr = acc > 0.f ? acc : 0.1f * acc;
        uint32_t u = __float_as_uint(lr);
        wsm2[tid] = ((uint64_t)u << 32) | u;
    }

    // ---- interior: sum 8 channels, write A (unaligned scalar) + B (aligned f4) ----
    // items: 34 padded rows x 64 float4 groups = 2176
    #pragma unroll
    for (int i = 0; i < 9; ++i) {
        int item = tid + i * 256;
        if (item < (TY + 2) * 64) {
            int r  = item >> 6;
            int j4 = item & 63;
            int y = tileY * TY + r - 1;
            y = (y < 0) ? 1 : (y > H - 1 ? H - 2 : y);   // reflect pad=1
            const float4* p = (const float4*)(xg + (size_t)y * WID + 4 * j4);
            float sx = 0.f, sy = 0.f, sz = 0.f, sw = 0.f;
            #pragma unroll
            for (int c = 0; c < FPG; ++c) {
                float4 v = p[c * (H * WID / 4)];
                sx += v.x; sy += v.y; sz += v.z; sw += v.w;
            }
            // A: s_padded[4j4+1 .. 4j4+4]
            float* dA = smA + r * SM_W + 4 * j4 + 1;
            dA[0] = sx; dA[1] = sy; dA[2] = sz; dA[3] = sw;
            // B: smB[r][4j4..4j4+3] = s_padded[4j4+1..4j4+4]  (same values, aligned)
            *(float4*)(smB + r * B_W + 4 * j4) = make_float4(sx, sy, sz, sw);
        }
    }
    // ---- halo columns (A only): padded col 0 <- x=1 ; padded col 257 <- x=254 ----
    if (tid < 2 * (TY + 2)) {
        int r = tid >> 1, side = tid & 1;
        int y = tileY * TY + r - 1;
        y = (y < 0) ? 1 : (y > H - 1 ? H - 2 : y);
        int xs = side ? (WID - 2) : 1;
        float v = 0.f;
        #pragma unroll
        for (int c = 0; c < FPG; ++c) v += xg[(size_t)c * (H * WID) + (size_t)y * WID + xs];
        smA[r * SM_W + (side ? 257 : 0)] = v;
    }
    __syncthreads();

    // ---- compute: 1x4 strips, 8 out channels, all pairs via aligned LDS.64 ----
    const int q  = tid & 63;   // outputs x = 4q .. 4q+3 ; window = padded cols 4q..4q+5
    const int r0 = tid >> 6;   // 0..3
    float* ob = out + ((size_t)(b * OUT_CH + g * FPG)) * (H * WID) + 4 * q;

    #pragma unroll 4
    for (int rr0 = 0; rr0 < TY; rr0 += 4) {
        const int rr = rr0 + r0;
        // p[dy][k] = (win[k], win[k+1]) : even k from A, odd k from B
        uint64_t p[3][5];
        #pragma unroll
        for (int dy = 0; dy < 3; ++dy) {
            const float* Ar = smA + (rr + dy) * SM_W + 4 * q;   // A[4q + .]
            const float* Br = smB + (rr + dy) * B_W + 4 * q;    // B[4q + .] = s[4q+1+.]
            p[dy][0] = *(const uint64_t*)(Ar + 0);   // (s4q,   s4q+1)
            p[dy][1] = *(const uint64_t*)(Br + 0);   // (s4q+1, s4q+2)
            p[dy][2] = *(const uint64_t*)(Ar + 2);   // (s4q+2, s4q+3)
            p[dy][3] = *(const uint64_t*)(Br + 2);   // (s4q+3, s4q+4)
            p[dy][4] = *(const uint64_t*)(Ar + 4);   // (s4q+4, s4q+5)
        }
        const int y = tileY * TY + rr;
        #pragma unroll
        for (int o = 0; o < 8; ++o) {
            uint64_t acc01 = 0ull, acc23 = 0ull;   // (ax,ay), (az,aw)
            #pragma unroll
            for (int dy = 0; dy < 3; ++dy) {
                #pragma unroll
                for (int dx = 0; dx < 3; ++dx) {
                    const uint64_t ww = wsm2[o * 9 + dy * 3 + dx];
                    fma2(acc01, p[dy][dx], ww);
                    fma2(acc23, p[dy][dx + 2], ww);
                }
            }
            float ax, ay, az, aw;
            unpk(ax, ay, acc01);
            unpk(az, aw, acc23);
            *(float4*)(ob + (size_t)o * (H * WID) + (size_t)y * WID) =
                make_float4(ax, ay, az, aw);
        }
    }
}

extern "C" void kernel_launch(void* const* d_in, const int* in_sizes, int n_in,
                              void* d_out, int out_size) {
    const float* x   = (const float*)d_in[0];
    const float* rep = (const float*)d_in[1];
    const float* W   = (const float*)d_in[2];
    float* out = (float*)d_out;

    cudaFuncSetAttribute(fused_conv_kernel,
                         cudaFuncAttributeMaxDynamicSharedMemorySize, SMEM_BYTES);

    dim3 grid(H / TY, GROUPS, BATCH);
    fused_conv_kernel<<<grid, 256, SMEM_BYTES>>>(x, rep, W, out);
}